// round 15
// baseline (speedup 1.0000x reference)
#include <cuda_runtime.h>
#include <cstdint>

// out[b,t,f] = relu( r2[t<16][f] + sum_c sign(x[b,t,c])*sign(w_sc[c,f]) )
//
// conv2's input is ste_sign(relu(...)) == +1 everywhere (sign(0)=+1), so the
// conv1 branch is dead and conv2+bn2 collapse to a per-f constant table (two
// variants: t<16 sees the causal zero-pad on the dilated tap). The shortcut is
// an exact +-1 binary GEMM via XOR+popcount.
//
// R15 (= R13 with the smem overflow fixed): SINGLE kernel launch. Block 0
// computes the 3KB table blob; its 2KB reduction scratch is OVERLAID inside
// the 48KB pipeline buffer (used strictly before any cp.async writes, phases
// separated by __syncthreads) so static smem stays at the 0xC000 limit.
// All blocks gate on a release/acquire flag (nanosleep spin); last finishing
// block resets flag+counter so every graph replay starts from identical
// state. Streaming body = R6's warp-private cp.async pipeline (42.2us).

#define EPSBN 1e-3f
#define NSTAGE 3
#define SROWS 4                        // rows per stage per warp
#define WARP_ROWS 32                   // rows per warp
#define SITER (WARP_ROWS / SROWS)      // 8 stage-iterations
#define ROWS_PER_BLOCK (8 * WARP_ROWS) // 256
#define TOTAL_ROWS (32 * 8192)         // 262144
#define GRID_BLOCKS (TOTAL_ROWS / ROWS_PER_BLOCK)   // 1024

__device__ uint4    g_wbits[128];  // f -> packed sign bits (word k bit l <-> channel 4l+k)
__device__ float    g_r2[2][128];  // folded (+128) bias tables: [0]=t>=16, [1]=t<16
__device__ unsigned g_flag = 0;    // tables-ready flag (reset each launch)
__device__ unsigned g_done = 0;    // finished-block counter (reset each launch)

__device__ __forceinline__ unsigned ld_acquire(unsigned* p) {
    unsigned v;
    asm volatile("ld.acquire.gpu.global.u32 %0, [%1];" : "=r"(v) : "l"(p) : "memory");
    return v;
}
__device__ __forceinline__ void st_release(unsigned* p, unsigned v) {
    asm volatile("st.release.gpu.global.u32 [%0], %1;" :: "l"(p), "r"(v) : "memory");
}

__device__ __forceinline__ void cp_async16(uint32_t smem_addr, const void* gptr) {
    asm volatile("cp.async.cg.shared.global [%0], [%1], 16;\n"
                 :: "r"(smem_addr), "l"(gptr));
}
__device__ __forceinline__ void cp_commit() {
    asm volatile("cp.async.commit_group;\n" ::: "memory");
}
template <int N>
__device__ __forceinline__ void cp_wait() {
    asm volatile("cp.async.wait_group %0;\n" :: "n"(N) : "memory");
}

__global__ void __launch_bounds__(256, 4)
resblock_fused(const float* __restrict__ x, float* __restrict__ out,
               const float* __restrict__ w2, const float* __restrict__ w_sc,
               const float* __restrict__ beta2, const float* __restrict__ mean2,
               const float* __restrict__ var2) {
    // [warp][stage][row][lane] float4 : 8*3*4*32*16 = 48 KB (== 0xC000 limit)
    __shared__ float4 s_x[8][NSTAGE][SROWS * 32];

    int tid  = threadIdx.x;
    int lane = tid & 31;
    int warp = tid >> 5;

    // ---------------- gate: block 0 builds tables, others wait ----------------
    if (blockIdx.x == 0) {
        // Overlay 2KB of reduction scratch at the start of s_x: this space is
        // only used HERE, before any cp.async writes (phases separated by the
        // __syncthreads below).
        int* sh01 = reinterpret_cast<int*>(&s_x[0][0][0]);   // [2][128]
        int* sh1  = sh01 + 256;                              // [2][128]

        int f = tid & 127;
        int h = tid >> 7;          // 0 or 1

        // Pack words h and h+2 of the shortcut-weight sign bits for column f.
        // (float4-ballot channel order: word k, bit l <-> channel 4l+k)
#pragma unroll
        for (int w2i = 0; w2i < 2; ++w2i) {
            int jw = h + 2 * w2i;
            unsigned w = 0u;
#pragma unroll
            for (int l = 0; l < 32; ++l) {
                if (w_sc[(4 * l + jw) * 128 + f] >= 0.f) w |= (1u << l);
            }
            reinterpret_cast<unsigned*>(&g_wbits[f])[jw] = w;
        }

        // Partial conv2 sign-sums: half h covers channels [64h, 64h+64)
        int S01 = 0, S1 = 0;
#pragma unroll 8
        for (int cc = 0; cc < 64; ++cc) {
            int c = 64 * h + cc;
            float a  = w2[c * 128 + f];           // tap k=0
            float bb = w2[16384 + c * 128 + f];   // tap k=1
            S01 += ((a >= 0.f) ? 1 : -1) + ((bb >= 0.f) ? 1 : -1);
            S1  += ((bb >= 0.f) ? 1 : -1);
        }
        sh01[h * 128 + f] = S01;
        sh1[h * 128 + f]  = S1;
        __syncthreads();

        if (tid < 128) {
            int t01 = sh01[f] + sh01[128 + f];
            int t1  = sh1[f]  + sh1[128 + f];
            float inv = rsqrtf(var2[f] + EPSBN);
            g_r2[0][f] = fmaxf(((float)t01 - mean2[f]) * inv + beta2[f], 0.f) + 128.f;
            g_r2[1][f] = fmaxf(((float)t1  - mean2[f]) * inv + beta2[f], 0.f) + 128.f;
        }
        __syncthreads();   // scratch dead after this point; s_x free for pipeline
        __threadfence();
        if (tid == 0) st_release(&g_flag, 1u);
    } else {
        if (tid == 0) {
            while (ld_acquire(&g_flag) == 0u) __nanosleep(128);
        }
        __syncthreads();
    }

    // ---------------- streaming body (R6 warp-private pipeline) ----------------
    uint4 wb0 = g_wbits[4 * lane + 0];
    uint4 wb1 = g_wbits[4 * lane + 1];
    uint4 wb2 = g_wbits[4 * lane + 2];
    uint4 wb3 = g_wbits[4 * lane + 3];
    float bP0 = g_r2[0][4 * lane + 0];
    float bP1 = g_r2[0][4 * lane + 1];
    float bP2 = g_r2[0][4 * lane + 2];
    float bP3 = g_r2[0][4 * lane + 3];

    size_t warp_row0 = (size_t)blockIdx.x * ROWS_PER_BLOCK + (size_t)warp * WARP_ROWS;
    const float4* __restrict__ gx = (const float4*)x + warp_row0 * 32 + lane;
    float4* __restrict__ o4 = (float4*)out;

    uint32_t sbase = (uint32_t)__cvta_generic_to_shared(&s_x[warp][0][0]);

    // prologue: issue stages 0 and 1 (each thread copies ONLY what it reads back)
#pragma unroll
    for (int s = 0; s < 2; ++s) {
#pragma unroll
        for (int r = 0; r < SROWS; ++r) {
            cp_async16(sbase + (uint32_t)((s * SROWS + r) * 32 + lane) * 16,
                       gx + (size_t)(s * SROWS + r) * 32);
        }
        cp_commit();
    }

#pragma unroll
    for (int s = 0; s < SITER; ++s) {
        if (s + 2 < SITER) {
            int ps = s + 2, b = ps % NSTAGE;
#pragma unroll
            for (int r = 0; r < SROWS; ++r) {
                cp_async16(sbase + (uint32_t)((b * SROWS + r) * 32 + lane) * 16,
                           gx + (size_t)(ps * SROWS + r) * 32);
            }
            cp_commit();
            cp_wait<2>();
        } else if (s == SITER - 2) {
            cp_wait<1>();
        } else {
            cp_wait<0>();
        }

        const float4* buf = s_x[warp][s % NSTAGE];
#pragma unroll
        for (int r = 0; r < SROWS; ++r) {
            float4 v = buf[r * 32 + lane];   // this thread's own cp.async result

            unsigned m0 = __ballot_sync(0xffffffffu, v.x >= 0.f);
            unsigned m1 = __ballot_sync(0xffffffffu, v.y >= 0.f);
            unsigned m2 = __ballot_sync(0xffffffffu, v.z >= 0.f);
            unsigned m3 = __ballot_sync(0xffffffffu, v.w >= 0.f);

            size_t row = warp_row0 + (size_t)(s * SROWS + r);

            float p0 = bP0, p1 = bP1, p2 = bP2, p3 = bP3;
            if ((row & 8191) < 16) {               // 512 of 262144 rows
                p0 = g_r2[1][4 * lane + 0];
                p1 = g_r2[1][4 * lane + 1];
                p2 = g_r2[1][4 * lane + 2];
                p3 = g_r2[1][4 * lane + 3];
            }

            int c0 = __popc(m0 ^ wb0.x) + __popc(m1 ^ wb0.y) + __popc(m2 ^ wb0.z) + __popc(m3 ^ wb0.w);
            int c1 = __popc(m0 ^ wb1.x) + __popc(m1 ^ wb1.y) + __popc(m2 ^ wb1.z) + __popc(m3 ^ wb1.w);
            int c2 = __popc(m0 ^ wb2.x) + __popc(m1 ^ wb2.y) + __popc(m2 ^ wb2.z) + __popc(m3 ^ wb2.w);
            int c3 = __popc(m0 ^ wb3.x) + __popc(m1 ^ wb3.y) + __popc(m2 ^ wb3.z) + __popc(m3 ^ wb3.w);

            float4 o;
            o.x = fmaxf(fmaf(-2.f, (float)c0, p0), 0.f);
            o.y = fmaxf(fmaf(-2.f, (float)c1, p1), 0.f);
            o.z = fmaxf(fmaf(-2.f, (float)c2, p2), 0.f);
            o.w = fmaxf(fmaf(-2.f, (float)c3, p3), 0.f);
            o4[row * 32 + lane] = o;
        }
    }

    // ---------------- epilogue: last block resets gate state ----------------
    __syncthreads();
    if (tid == 0) {
        unsigned n = atomicAdd(&g_done, 1u);
        if (n == (unsigned)(gridDim.x - 1)) {
            g_done = 0u;
            st_release(&g_flag, 0u);   // next launch (replay) sees clean state
        }
    }
}

extern "C" void kernel_launch(void* const* d_in, const int* in_sizes, int n_in,
                              void* d_out, int out_size) {
    const float* x     = (const float*)d_in[0];
    // d_in[1] = w1 (dead), d_in[4..6] = bn1 params (dead)
    const float* w2    = (const float*)d_in[2];
    const float* w_sc  = (const float*)d_in[3];
    const float* beta2 = (const float*)d_in[7];
    const float* mean2 = (const float*)d_in[8];
    const float* var2  = (const float*)d_in[9];
    float* out = (float*)d_out;

    resblock_fused<<<GRID_BLOCKS, 256>>>(x, out, w2, w_sc, beta2, mean2, var2);
}

// round 16
// speedup vs baseline: 1.1042x; 1.1042x over previous
#include <cuda_runtime.h>
#include <cstdint>

// out[b,t,f] = relu( r2[t<16][f] + sum_c sign(x[b,t,c])*sign(w_sc[c,f]) )
//
// conv2's input is ste_sign(relu(...)) == +1 everywhere (sign(0)=+1), so the
// conv1 branch is dead and conv2+bn2 collapse to a per-f constant table (two
// variants: t<16 sees the causal zero-pad on the dilated tap). The shortcut is
// an exact +-1 binary GEMM via XOR+popcount.
//
// R16: single launch, DISTRIBUTED gate (v1's 7.4us gate tax came from a
// 1-block table build serializing the whole first wave). Blocks 0-7 build
// partial sign-sums (0-3 also pack weight words) -> fence -> count; block 8
// finalizes the bias tables and releases the flag; everyone spins briefly
// (~2us) then runs the R6 warp-private cp.async streaming body (42.2us).
// Last finishing block resets all gate state so every graph replay is
// identical. Static smem stays at exactly 48KB.

#define EPSBN 1e-3f
#define NSTAGE 3
#define SROWS 4                        // rows per stage per warp
#define WARP_ROWS 32                   // rows per warp
#define SITER (WARP_ROWS / SROWS)      // 8 stage-iterations
#define ROWS_PER_BLOCK (8 * WARP_ROWS) // 256
#define TOTAL_ROWS (32 * 8192)         // 262144
#define GRID_BLOCKS (TOTAL_ROWS / ROWS_PER_BLOCK)   // 1024

__device__ uint4    g_wbits[128];       // f -> packed sign bits (word k bit l <-> channel 4l+k)
__device__ float    g_r2[2][128];       // folded (+128) bias tables: [0]=t>=16, [1]=t<16
__device__ int      g_part[8][2][128];  // partial conv2 sign-sums per 16-channel slice
__device__ unsigned g_cnt  = 0;         // builder arrivals (reset by finalizer)
__device__ unsigned g_flag = 0;         // tables-ready flag (reset by last block)
__device__ unsigned g_done = 0;         // finished-block counter (reset by last block)

__device__ __forceinline__ unsigned ld_acquire(unsigned* p) {
    unsigned v;
    asm volatile("ld.acquire.gpu.global.u32 %0, [%1];" : "=r"(v) : "l"(p) : "memory");
    return v;
}
__device__ __forceinline__ void st_release(unsigned* p, unsigned v) {
    asm volatile("st.release.gpu.global.u32 [%0], %1;" :: "l"(p), "r"(v) : "memory");
}

__device__ __forceinline__ void cp_async16(uint32_t smem_addr, const void* gptr) {
    asm volatile("cp.async.cg.shared.global [%0], [%1], 16;\n"
                 :: "r"(smem_addr), "l"(gptr));
}
__device__ __forceinline__ void cp_commit() {
    asm volatile("cp.async.commit_group;\n" ::: "memory");
}
template <int N>
__device__ __forceinline__ void cp_wait() {
    asm volatile("cp.async.wait_group %0;\n" :: "n"(N) : "memory");
}

__global__ void __launch_bounds__(256, 4)
resblock_fused(const float* __restrict__ x, float* __restrict__ out,
               const float* __restrict__ w2, const float* __restrict__ w_sc,
               const float* __restrict__ beta2, const float* __restrict__ mean2,
               const float* __restrict__ var2) {
    // [warp][stage][row][lane] float4 : 8*3*4*32*16 = 48 KB (== static limit)
    __shared__ float4 s_x[8][NSTAGE][SROWS * 32];

    int tid  = threadIdx.x;
    int lane = tid & 31;
    int warp = tid >> 5;
    int bx   = blockIdx.x;

    // ---------------- distributed gate ----------------
    if (bx < 8) {
        // Builder block b: partial conv2 sign-sums for channels [16b, 16b+16),
        // and (b<4) pack weight word b (float4-ballot order: word k, bit l <-> ch 4l+k).
        if (tid < 128) {
            int f = tid;
            if (bx < 4) {
                unsigned w = 0u;
#pragma unroll
                for (int l = 0; l < 32; ++l) {
                    if (w_sc[(4 * l + bx) * 128 + f] >= 0.f) w |= (1u << l);
                }
                reinterpret_cast<unsigned*>(&g_wbits[f])[bx] = w;
            }
            int S01 = 0, S1 = 0;
#pragma unroll
            for (int cc = 0; cc < 16; ++cc) {
                int c = 16 * bx + cc;
                float a  = w2[c * 128 + f];           // tap k=0
                float bb = w2[16384 + c * 128 + f];   // tap k=1
                S01 += ((a >= 0.f) ? 1 : -1) + ((bb >= 0.f) ? 1 : -1);
                S1  += ((bb >= 0.f) ? 1 : -1);
            }
            g_part[bx][0][f] = S01;
            g_part[bx][1][f] = S1;
        }
        __syncthreads();
        if (tid == 0) {
            __threadfence();
            atomicAdd(&g_cnt, 1u);
        }
    } else if (bx == 8) {
        // Finalizer: wait for all 8 builders, build bias tables, release flag.
        if (tid == 0) {
            while (ld_acquire(&g_cnt) < 8u) __nanosleep(32);
        }
        __syncthreads();
        if (tid < 128) {
            int f = tid;
            int t01 = 0, t1 = 0;
#pragma unroll
            for (int j = 0; j < 8; ++j) { t01 += g_part[j][0][f]; t1 += g_part[j][1][f]; }
            float inv = rsqrtf(var2[f] + EPSBN);
            g_r2[0][f] = fmaxf(((float)t01 - mean2[f]) * inv + beta2[f], 0.f) + 128.f;
            g_r2[1][f] = fmaxf(((float)t1  - mean2[f]) * inv + beta2[f], 0.f) + 128.f;
        }
        __syncthreads();
        if (tid == 0) {
            g_cnt = 0u;                 // reset for next replay (pre-flag, fenced below)
            __threadfence();
            st_release(&g_flag, 1u);
        }
    }

    // Everyone waits for tables (builders + finalizer included; flag release
    // orders all table writes before any reader below).
    if (tid == 0) {
        while (ld_acquire(&g_flag) == 0u) __nanosleep(32);
    }
    __syncthreads();

    // ---------------- streaming body (R6 warp-private pipeline) ----------------
    uint4 wb0 = g_wbits[4 * lane + 0];
    uint4 wb1 = g_wbits[4 * lane + 1];
    uint4 wb2 = g_wbits[4 * lane + 2];
    uint4 wb3 = g_wbits[4 * lane + 3];
    float bP0 = g_r2[0][4 * lane + 0];
    float bP1 = g_r2[0][4 * lane + 1];
    float bP2 = g_r2[0][4 * lane + 2];
    float bP3 = g_r2[0][4 * lane + 3];

    size_t warp_row0 = (size_t)bx * ROWS_PER_BLOCK + (size_t)warp * WARP_ROWS;
    const float4* __restrict__ gx = (const float4*)x + warp_row0 * 32 + lane;
    float4* __restrict__ o4 = (float4*)out;

    uint32_t sbase = (uint32_t)__cvta_generic_to_shared(&s_x[warp][0][0]);

    // prologue: issue stages 0 and 1 (each thread copies ONLY what it reads back)
#pragma unroll
    for (int s = 0; s < 2; ++s) {
#pragma unroll
        for (int r = 0; r < SROWS; ++r) {
            cp_async16(sbase + (uint32_t)((s * SROWS + r) * 32 + lane) * 16,
                       gx + (size_t)(s * SROWS + r) * 32);
        }
        cp_commit();
    }

#pragma unroll
    for (int s = 0; s < SITER; ++s) {
        if (s + 2 < SITER) {
            int ps = s + 2, b = ps % NSTAGE;
#pragma unroll
            for (int r = 0; r < SROWS; ++r) {
                cp_async16(sbase + (uint32_t)((b * SROWS + r) * 32 + lane) * 16,
                           gx + (size_t)(ps * SROWS + r) * 32);
            }
            cp_commit();
            cp_wait<2>();
        } else if (s == SITER - 2) {
            cp_wait<1>();
        } else {
            cp_wait<0>();
        }

        const float4* buf = s_x[warp][s % NSTAGE];
#pragma unroll
        for (int r = 0; r < SROWS; ++r) {
            float4 v = buf[r * 32 + lane];   // this thread's own cp.async result

            unsigned m0 = __ballot_sync(0xffffffffu, v.x >= 0.f);
            unsigned m1 = __ballot_sync(0xffffffffu, v.y >= 0.f);
            unsigned m2 = __ballot_sync(0xffffffffu, v.z >= 0.f);
            unsigned m3 = __ballot_sync(0xffffffffu, v.w >= 0.f);

            size_t row = warp_row0 + (size_t)(s * SROWS + r);

            float p0 = bP0, p1 = bP1, p2 = bP2, p3 = bP3;
            if ((row & 8191) < 16) {               // 512 of 262144 rows
                p0 = g_r2[1][4 * lane + 0];
                p1 = g_r2[1][4 * lane + 1];
                p2 = g_r2[1][4 * lane + 2];
                p3 = g_r2[1][4 * lane + 3];
            }

            int c0 = __popc(m0 ^ wb0.x) + __popc(m1 ^ wb0.y) + __popc(m2 ^ wb0.z) + __popc(m3 ^ wb0.w);
            int c1 = __popc(m0 ^ wb1.x) + __popc(m1 ^ wb1.y) + __popc(m2 ^ wb1.z) + __popc(m3 ^ wb1.w);
            int c2 = __popc(m0 ^ wb2.x) + __popc(m1 ^ wb2.y) + __popc(m2 ^ wb2.z) + __popc(m3 ^ wb2.w);
            int c3 = __popc(m0 ^ wb3.x) + __popc(m1 ^ wb3.y) + __popc(m2 ^ wb3.z) + __popc(m3 ^ wb3.w);

            float4 o;
            o.x = fmaxf(fmaf(-2.f, (float)c0, p0), 0.f);
            o.y = fmaxf(fmaf(-2.f, (float)c1, p1), 0.f);
            o.z = fmaxf(fmaf(-2.f, (float)c2, p2), 0.f);
            o.w = fmaxf(fmaf(-2.f, (float)c3, p3), 0.f);
            o4[row * 32 + lane] = o;
        }
    }

    // ---------------- epilogue: last block resets gate state ----------------
    __syncthreads();
    if (tid == 0) {
        unsigned n = atomicAdd(&g_done, 1u);
        if (n == (unsigned)(gridDim.x - 1)) {
            g_done = 0u;
            st_release(&g_flag, 0u);   // next launch (replay) sees clean state
        }
    }
}

extern "C" void kernel_launch(void* const* d_in, const int* in_sizes, int n_in,
                              void* d_out, int out_size) {
    const float* x     = (const float*)d_in[0];
    // d_in[1] = w1 (dead), d_in[4..6] = bn1 params (dead)
    const float* w2    = (const float*)d_in[2];
    const float* w_sc  = (const float*)d_in[3];
    const float* beta2 = (const float*)d_in[7];
    const float* mean2 = (const float*)d_in[8];
    const float* var2  = (const float*)d_in[9];
    float* out = (float*)d_out;

    resblock_fused<<<GRID_BLOCKS, 256>>>(x, out, w2, w_sc, beta2, mean2, var2);
}